// round 13
// baseline (speedup 1.0000x reference)
#include <cuda_runtime.h>
#include <cuda_bf16.h>
#include <cstdint>

#define TOTPTS 16384
#define NPTS   4096
#define KNN    16

// ---- knn-mma config ----
#define KQ   16                  // queries per block (one m16 tile)
#define CT   512                 // candidate tile in smem
#define NT   (NPTS / CT)         // 8 tiles
#define CAP  256                 // buffer capacity per query (fallback if exceeded)
#define MARGIN 0.05f             // >= 2*err bound for 3-term bf16 split

// ---- edge_mlp smem: weights only ----
#define WBYTES  50176            // 64*392*2
#define MAIN_SMEM_BYTES 100352   // hi + lo

// Scratch (allocation-free rule: device globals)
__device__ __align__(16) float g_L[TOTPTS * 256];   // [P | R1 | R2 | R3] per point
__device__ __align__(16) float g_Q[TOTPTS * 64];    // Q per point
__device__ int g_idx[TOTPTS * KNN];
__device__ __align__(16) unsigned char g_Wpk[100352]; // packed bf16 hi/lo weights
__device__ int g_buf[TOTPTS * CAP];                  // knn candidate buffer (16.8 MB)

// ===================== helpers =====================
__device__ __forceinline__ uint32_t smem_to_u32(const void* p) {
    uint32_t a;
    asm("{ .reg .u64 t; cvta.to.shared.u64 t, %1; cvt.u32.u64 %0, t; }" : "=r"(a) : "l"(p));
    return a;
}
#define LDSM4(r0, r1, r2, r3, addr) \
    asm volatile("ldmatrix.sync.aligned.m8n8.x4.shared.b16 {%0,%1,%2,%3}, [%4];" \
        : "=r"(r0), "=r"(r1), "=r"(r2), "=r"(r3) : "r"(addr))
#define MMA16816(c, a0, a1, a2, a3, b0, b1) \
    asm volatile("mma.sync.aligned.m16n8k16.row.col.f32.bf16.bf16.f32 " \
        "{%0,%1,%2,%3}, {%4,%5,%6,%7}, {%8,%9}, {%0,%1,%2,%3};" \
        : "+f"((c)[0]), "+f"((c)[1]), "+f"((c)[2]), "+f"((c)[3]) \
        : "r"(a0), "r"(a1), "r"(a2), "r"(a3), "r"(b0), "r"(b1))

__device__ __forceinline__ void hilo2(float a, float b, uint32_t& h, uint32_t& l) {
    __nv_bfloat16 ha = __float2bfloat16(a), hb = __float2bfloat16(b);
    float ra = a - __bfloat162float(ha), rb = b - __bfloat162float(hb);
    __nv_bfloat162 H; H.x = ha; H.y = hb;
    __nv_bfloat162 L; L.x = __float2bfloat16(ra); L.y = __float2bfloat16(rb);
    h = *(uint32_t*)&H; l = *(uint32_t*)&L;
}
__device__ __forceinline__ void bfsplit(float x, unsigned short& h, unsigned short& l) {
    __nv_bfloat16 hb = __float2bfloat16(x);
    float r = x - __bfloat162float(hb);
    h = __bfloat16_as_ushort(hb);
    l = __bfloat16_as_ushort(__float2bfloat16(r));
}

// top-4 replace-max insert (exclude self)
#define INS4(arr, mx, mi, kk, cd, qs) do { \
    if ((kk) < (mx) && (cd) != (qs)) { \
        (arr)[(mi)] = (kk); \
        (mx) = (arr)[0]; (mi) = 0; \
        if ((arr)[1] > (mx)) { (mx) = (arr)[1]; (mi) = 1; } \
        if ((arr)[2] > (mx)) { (mx) = (arr)[2]; (mi) = 2; } \
        if ((arr)[3] > (mx)) { (mx) = (arr)[3]; (mi) = 3; } \
    } } while (0)

// ---------------------------------------------------------------------------
// KNN via tensor cores. Block = 128 thr = 4 warps sharing one m16 query tile;
// warps split candidates 4-way. Phase A: mma keys -> per-lane exact top-4 of
// its stripe (self excluded). Per warp: max over 4 tc-lanes of lane-4th =
// bound on d16 within the warp's 1024-candidate subset; min over warps is a
// valid (tight) bound on global d16. Phase B: mma filter key < tau + MARGIN
// (covers split error) -> buffer. Refine: exact fp32 formula (identical to
// all passing rounds) over buffer -> bit-identical selection. n>CAP falls
// back to exact full scan (unconditional correctness).
// ---------------------------------------------------------------------------
__global__ __launch_bounds__(128) void knn_kernel(const float* __restrict__ pos) {
    __shared__ __align__(16) unsigned short sC[CT * 16];  // cand k-vectors, 16 KB
    __shared__ __align__(8)  float sCN[CT];               // cand norms fp32, 2 KB
    __shared__ __align__(16) unsigned short sA[KQ * 16];  // query k-vectors, 512 B
    __shared__ float sTauW[4][KQ];
    __shared__ float sTau[KQ];
    __shared__ int   scnt[KQ];

    int t = threadIdx.x, lane = t & 31, w = t >> 5;
    int qg0 = blockIdx.x * KQ;
    int b   = qg0 >> 12, qb0 = qg0 & 4095;
    const float* pb = pos + b * NPTS * 3;

    // Build A: slots [qxh qyh qzh | qxl qyl qzl | qxh qyh qzh | 0..]
    if (t < KQ) {
        int q = qb0 + t;
        float x = pb[q * 3 + 0], y = pb[q * 3 + 1], z = pb[q * 3 + 2];
        unsigned short xh, xl, yh, yl, zh, zl;
        bfsplit(x, xh, xl); bfsplit(y, yh, yl); bfsplit(z, zh, zl);
        unsigned short* row = sA + t * 16;
        uint32_t u0 = (uint32_t)xh | ((uint32_t)yh << 16);
        uint32_t u1 = (uint32_t)zh | ((uint32_t)xl << 16);
        uint32_t u2 = (uint32_t)yl | ((uint32_t)zl << 16);
        uint32_t u3 = (uint32_t)xh | ((uint32_t)yh << 16);
        *(uint4*)(row)     = make_uint4(u0, u1, u2, u3);
        *(uint4*)(row + 8) = make_uint4((uint32_t)zh, 0u, 0u, 0u);
        scnt[t] = 0;
    }
    __syncthreads();

    uint32_t aAddr = smem_to_u32(sA) + (lane & 15) * 32 + (lane >> 4) * 16;
    uint32_t a0, a1, a2, a3;
    LDSM4(a0, a1, a2, a3, aAddr);

    int tg = lane >> 2, tc = lane & 3;
    int q1 = qb0 + tg, q2 = q1 + 8;

    uint32_t bBase0 = (w * 128 + (lane & 7) + ((lane >> 4) & 1) * 8) * 32
                      + ((lane >> 3) & 1) * 16;

    // ---- Phase A ----
    float t4a[4] = {3e38f, 3e38f, 3e38f, 3e38f};
    float t4b[4] = {3e38f, 3e38f, 3e38f, 3e38f};
    float mxa = 3e38f, mxb = 3e38f;
    int mia = 0, mib = 0;

    for (int tile = 0; tile < NT; tile++) {
        int tile0 = tile * CT;
        __syncthreads();
        for (int i = t; i < CT; i += 128) {
            int j = tile0 + i;
            float x = pb[j * 3 + 0], y = pb[j * 3 + 1], z = pb[j * 3 + 2];
            sCN[i] = x * x + y * y + z * z;
            unsigned short xh, xl, yh, yl, zh, zl;
            bfsplit(x, xh, xl); bfsplit(y, yh, yl); bfsplit(z, zh, zl);
            unsigned short* row = sC + i * 16;
            // slots [cxh cyh czh | cxh cyh czh | cxl cyl czl | 0..]
            uint32_t u0 = (uint32_t)xh | ((uint32_t)yh << 16);
            uint32_t u1 = (uint32_t)zh | ((uint32_t)xh << 16);
            uint32_t u2 = (uint32_t)yh | ((uint32_t)zh << 16);
            uint32_t u3 = (uint32_t)xl | ((uint32_t)yl << 16);
            *(uint4*)(row)     = make_uint4(u0, u1, u2, u3);
            *(uint4*)(row + 8) = make_uint4((uint32_t)zl, 0u, 0u, 0u);
        }
        __syncthreads();
        uint32_t bAddr = smem_to_u32(sC) + bBase0;
#pragma unroll 2
        for (int c0 = 0; c0 < 128; c0 += 16) {
            uint32_t b0, b1, b2, b3;
            LDSM4(b0, b1, b2, b3, bAddr + c0 * 32);
            float ac0[4] = {0.f, 0.f, 0.f, 0.f};
            float ac1[4] = {0.f, 0.f, 0.f, 0.f};
            MMA16816(ac0, a0, a1, a2, a3, b0, b1);
            MMA16816(ac1, a0, a1, a2, a3, b2, b3);
            int cb = w * 128 + c0;
            float2 cn0 = *(float2*)&sCN[cb + 2 * tc];
            float2 cn1 = *(float2*)&sCN[cb + 8 + 2 * tc];
            int cA = tile0 + cb + 2 * tc, cB = cA + 8;
            float k00 = fmaf(ac0[0], -2.f, cn0.x);
            float k01 = fmaf(ac0[1], -2.f, cn0.y);
            float k10 = fmaf(ac1[0], -2.f, cn1.x);
            float k11 = fmaf(ac1[1], -2.f, cn1.y);
            float k02 = fmaf(ac0[2], -2.f, cn0.x);
            float k03 = fmaf(ac0[3], -2.f, cn0.y);
            float k12 = fmaf(ac1[2], -2.f, cn1.x);
            float k13 = fmaf(ac1[3], -2.f, cn1.y);
            INS4(t4a, mxa, mia, k00, cA, q1);
            INS4(t4a, mxa, mia, k01, cA + 1, q1);
            INS4(t4a, mxa, mia, k10, cB, q1);
            INS4(t4a, mxa, mia, k11, cB + 1, q1);
            INS4(t4b, mxb, mib, k02, cA, q2);
            INS4(t4b, mxb, mib, k03, cA + 1, q2);
            INS4(t4b, mxb, mib, k12, cB, q2);
            INS4(t4b, mxb, mib, k13, cB + 1, q2);
        }
    }

    // per-warp bound: max over the 4 tc lanes (16 distinct elems of warp
    // subset). Across warps take MIN (each warp bound is valid alone).
    float ra = mxa;
    ra = fmaxf(ra, __shfl_xor_sync(0xffffffffu, ra, 1));
    ra = fmaxf(ra, __shfl_xor_sync(0xffffffffu, ra, 2));
    float rb = mxb;
    rb = fmaxf(rb, __shfl_xor_sync(0xffffffffu, rb, 1));
    rb = fmaxf(rb, __shfl_xor_sync(0xffffffffu, rb, 2));
    if (tc == 0) { sTauW[w][tg] = ra; sTauW[w][tg + 8] = rb; }
    __syncthreads();
    if (t < KQ)
        sTau[t] = fminf(fminf(sTauW[0][t], sTauW[1][t]),
                        fminf(sTauW[2][t], sTauW[3][t])) + MARGIN;
    __syncthreads();
    float tauA = sTau[tg], tauB = sTau[tg + 8];

    // ---- Phase B: filter + buffer ----
    for (int tile = 0; tile < NT; tile++) {
        int tile0 = tile * CT;
        __syncthreads();
        for (int i = t; i < CT; i += 128) {
            int j = tile0 + i;
            float x = pb[j * 3 + 0], y = pb[j * 3 + 1], z = pb[j * 3 + 2];
            sCN[i] = x * x + y * y + z * z;
            unsigned short xh, xl, yh, yl, zh, zl;
            bfsplit(x, xh, xl); bfsplit(y, yh, yl); bfsplit(z, zh, zl);
            unsigned short* row = sC + i * 16;
            uint32_t u0 = (uint32_t)xh | ((uint32_t)yh << 16);
            uint32_t u1 = (uint32_t)zh | ((uint32_t)xh << 16);
            uint32_t u2 = (uint32_t)yh | ((uint32_t)zh << 16);
            uint32_t u3 = (uint32_t)xl | ((uint32_t)yl << 16);
            *(uint4*)(row)     = make_uint4(u0, u1, u2, u3);
            *(uint4*)(row + 8) = make_uint4((uint32_t)zl, 0u, 0u, 0u);
        }
        __syncthreads();
        uint32_t bAddr = smem_to_u32(sC) + bBase0;
#pragma unroll 2
        for (int c0 = 0; c0 < 128; c0 += 16) {
            uint32_t b0, b1, b2, b3;
            LDSM4(b0, b1, b2, b3, bAddr + c0 * 32);
            float ac0[4] = {0.f, 0.f, 0.f, 0.f};
            float ac1[4] = {0.f, 0.f, 0.f, 0.f};
            MMA16816(ac0, a0, a1, a2, a3, b0, b1);
            MMA16816(ac1, a0, a1, a2, a3, b2, b3);
            int cb = w * 128 + c0;
            float2 cn0 = *(float2*)&sCN[cb + 2 * tc];
            float2 cn1 = *(float2*)&sCN[cb + 8 + 2 * tc];
            int cA = tile0 + cb + 2 * tc, cB = cA + 8;
            float k00 = fmaf(ac0[0], -2.f, cn0.x);
            float k01 = fmaf(ac0[1], -2.f, cn0.y);
            float k10 = fmaf(ac1[0], -2.f, cn1.x);
            float k11 = fmaf(ac1[1], -2.f, cn1.y);
            float k02 = fmaf(ac0[2], -2.f, cn0.x);
            float k03 = fmaf(ac0[3], -2.f, cn0.y);
            float k12 = fmaf(ac1[2], -2.f, cn1.x);
            float k13 = fmaf(ac1[3], -2.f, cn1.y);
            if (k00 < tauA) { int s = atomicAdd(&scnt[tg], 1);     if (s < CAP) g_buf[(qg0 + tg) * CAP + s] = cA; }
            if (k01 < tauA) { int s = atomicAdd(&scnt[tg], 1);     if (s < CAP) g_buf[(qg0 + tg) * CAP + s] = cA + 1; }
            if (k10 < tauA) { int s = atomicAdd(&scnt[tg], 1);     if (s < CAP) g_buf[(qg0 + tg) * CAP + s] = cB; }
            if (k11 < tauA) { int s = atomicAdd(&scnt[tg], 1);     if (s < CAP) g_buf[(qg0 + tg) * CAP + s] = cB + 1; }
            if (k02 < tauB) { int s = atomicAdd(&scnt[tg + 8], 1); if (s < CAP) g_buf[(qg0 + tg + 8) * CAP + s] = cA; }
            if (k03 < tauB) { int s = atomicAdd(&scnt[tg + 8], 1); if (s < CAP) g_buf[(qg0 + tg + 8) * CAP + s] = cA + 1; }
            if (k12 < tauB) { int s = atomicAdd(&scnt[tg + 8], 1); if (s < CAP) g_buf[(qg0 + tg + 8) * CAP + s] = cB; }
            if (k13 < tauB) { int s = atomicAdd(&scnt[tg + 8], 1); if (s < CAP) g_buf[(qg0 + tg + 8) * CAP + s] = cB + 1; }
        }
    }
    __syncthreads();

    // ---- Refine: exact fp32, identical formula to all passing rounds ----
    if (t < KQ) {
        int qg = qg0 + t, q = qb0 + t;
        float qx = pb[q * 3 + 0], qy = pb[q * 3 + 1], qz = pb[q * 3 + 2];
        float qn = qx * qx + qy * qy + qz * qz;
        float dv[KNN];
        int   iv[KNN];
#pragma unroll
        for (int r = 0; r < KNN; r++) { dv[r] = 3.0e38f; iv[r] = 0; }
        float dmax = 3.0e38f;
        int   amax = 0;
        int n = scnt[t];
        if (n > CAP) {
            for (int j = 0; j < NPTS; j++) {
                if (j == q) continue;
                float cx = pb[j * 3], cy = pb[j * 3 + 1], cz = pb[j * 3 + 2];
                float cn = cx * cx + cy * cy + cz * cz;
                float dot = qx * cx;
                dot = fmaf(qy, cy, dot);
                dot = fmaf(qz, cz, dot);
                float d2 = fmaf(dot, -2.0f, qn + cn);
                if (d2 < dmax) {
                    dv[amax] = d2; iv[amax] = j;
                    dmax = dv[0]; amax = 0;
#pragma unroll
                    for (int r = 1; r < KNN; r++)
                        if (dv[r] > dmax) { dmax = dv[r]; amax = r; }
                }
            }
        } else {
            const int* bp = g_buf + qg * CAP;
            for (int e = 0; e < n; e++) {
                int j = bp[e];
                if (j == q) continue;
                float cx = pb[j * 3], cy = pb[j * 3 + 1], cz = pb[j * 3 + 2];
                float cn = cx * cx + cy * cy + cz * cz;
                float dot = qx * cx;
                dot = fmaf(qy, cy, dot);
                dot = fmaf(qz, cz, dot);
                float d2 = fmaf(dot, -2.0f, qn + cn);
                if (d2 < dmax) {
                    dv[amax] = d2; iv[amax] = j;
                    dmax = dv[0]; amax = 0;
#pragma unroll
                    for (int r = 1; r < KNN; r++)
                        if (dv[r] > dmax) { dmax = dv[r]; amax = r; }
                }
            }
        }
#pragma unroll
        for (int r = 0; r < KNN; r++) g_idx[qg * KNN + r] = iv[r];
    }
}

// ---------------------------------------------------------------------------
// Per-point precompute (unchanged)
// ---------------------------------------------------------------------------
__global__ __launch_bounds__(256) void pre_kernel(
    const float* __restrict__ x,
    const float* __restrict__ Wf,  const float* __restrict__ bf,
    const float* __restrict__ Wm1, const float* __restrict__ bm1,
    const float* __restrict__ Wm2, const float* __restrict__ bm2,
    const float* __restrict__ Wl,  const float* __restrict__ bl) {

    __shared__ float sw[4096];
    __shared__ float sx[64 * 68];

    int t   = threadIdx.x;
    int pt0 = blockIdx.x * 64;

    for (int i = t; i < 4096; i += 256) {
        int r = i >> 6, c = i & 63;
        sx[c * 68 + r] = __ldg(x + (pt0 + r) * 64 + c);
    }

    int m0 = (t & 15) * 4;
    int n0 = (t >> 4) * 4;

    for (int sect = 0; sect < 5; sect++) {
        __syncthreads();
        for (int i = t; i < 4096; i += 256) {
            float v;
            if      (sect == 0) v = __ldg(Wf + i)        - __ldg(Wf + 8192 + i);
            else if (sect == 1) v = __ldg(Wf + 4096 + i) + __ldg(Wf + 8192 + i);
            else if (sect == 2) v = __ldg(Wm1 + 4096 + i);
            else if (sect == 3) v = __ldg(Wm2 + 8192 + i);
            else                v = __ldg(Wl + 12288 + i);
            sw[i] = v;
        }
        __syncthreads();

        float acc[4][4];
#pragma unroll
        for (int a = 0; a < 4; a++)
#pragma unroll
            for (int bq = 0; bq < 4; bq++) acc[a][bq] = 0.0f;

#pragma unroll 4
        for (int k = 0; k < 64; k++) {
            float4 av = *(const float4*)(sx + k * 68 + m0);
            float4 wv = *(const float4*)(sw + k * 64 + n0);
            float aa[4] = {av.x, av.y, av.z, av.w};
            float ww[4] = {wv.x, wv.y, wv.z, wv.w};
#pragma unroll
            for (int mi = 0; mi < 4; mi++)
#pragma unroll
                for (int ni = 0; ni < 4; ni++)
                    acc[mi][ni] = fmaf(aa[mi], ww[ni], acc[mi][ni]);
        }

        float4 bb = make_float4(0.f, 0.f, 0.f, 0.f);
        const float* bp = (sect == 0) ? bf : (sect == 2) ? bm1
                         : (sect == 3) ? bm2 : (sect == 4) ? bl : nullptr;
        if (bp) bb = __ldg((const float4*)(bp + n0));

#pragma unroll
        for (int mi = 0; mi < 4; mi++) {
            int pt = pt0 + m0 + mi;
            float4 o = make_float4(acc[mi][0] + bb.x, acc[mi][1] + bb.y,
                                   acc[mi][2] + bb.z, acc[mi][3] + bb.w);
            float* dst;
            if (sect == 1) dst = g_Q + pt * 64 + n0;
            else {
                int off = (sect == 0) ? 0 : (sect == 2) ? 64 : (sect == 3) ? 128 : 192;
                dst = g_L + pt * 256 + off + n0;
            }
            *(float4*)dst = o;
        }
    }
}

// ---------------------------------------------------------------------------
// Weight repack (unchanged)
// ---------------------------------------------------------------------------
__global__ __launch_bounds__(256) void init_w_kernel(
    const float* __restrict__ Wm1, const float* __restrict__ Wm2,
    const float* __restrict__ Wl) {
    int e = blockIdx.x * 256 + threadIdx.x;          // 0..24575
    const float* src; int colbase;
    if (e < 4096)       { src = Wm1; colbase = 0; }
    else if (e < 12288) { src = Wm2; colbase = 64;  e -= 4096; }
    else                { src = Wl;  colbase = 192; e -= 12288; }
    int k = e >> 6, n = e & 63;
    float v = src[k * 64 + n];
    __nv_bfloat16 h = __float2bfloat16(v);
    __nv_bfloat16 l = __float2bfloat16(v - __bfloat162float(h));
    uint32_t off = (uint32_t)(n * 392 + colbase + k) * 2;
    *(__nv_bfloat16*)(g_Wpk + off)         = h;
    *(__nv_bfloat16*)(g_Wpk + 50176 + off) = l;
}

// ---------------------------------------------------------------------------
// edge_mlp (unchanged R10 winner)
// ---------------------------------------------------------------------------
__device__ __forceinline__ void mma_chunk(
    uint32_t a0h, uint32_t a1h, uint32_t a2h, uint32_t a3h,
    uint32_t a0l, uint32_t a1l, uint32_t a2l, uint32_t a3l,
    uint32_t bH, uint32_t bL, float acc[8][4]) {
    uint32_t bh[4][4], bl[4][4];
#pragma unroll
    for (int pr = 0; pr < 4; pr++) {
        LDSM4(bh[pr][0], bh[pr][1], bh[pr][2], bh[pr][3], bH + pr * (16 * 784));
        LDSM4(bl[pr][0], bl[pr][1], bl[pr][2], bl[pr][3], bL + pr * (16 * 784));
    }
#pragma unroll
    for (int pr = 0; pr < 4; pr++) {
        MMA16816(acc[2 * pr],     a0h, a1h, a2h, a3h, bh[pr][0], bh[pr][1]);
        MMA16816(acc[2 * pr + 1], a0h, a1h, a2h, a3h, bh[pr][2], bh[pr][3]);
    }
#pragma unroll
    for (int pr = 0; pr < 4; pr++) {
        MMA16816(acc[2 * pr],     a0h, a1h, a2h, a3h, bl[pr][0], bl[pr][1]);
        MMA16816(acc[2 * pr + 1], a0h, a1h, a2h, a3h, bl[pr][2], bl[pr][3]);
    }
#pragma unroll
    for (int pr = 0; pr < 4; pr++) {
        MMA16816(acc[2 * pr],     a0l, a1l, a2l, a3l, bh[pr][0], bh[pr][1]);
        MMA16816(acc[2 * pr + 1], a0l, a1l, a2l, a3l, bh[pr][2], bh[pr][3]);
    }
}

__device__ __forceinline__ void epi(
    float acc[8][4], const float* __restrict__ Rbase, bool do_relu,
    uint32_t* fh, uint32_t* fl, bool store,
    float* __restrict__ outp, int lane) {
    int tg = lane >> 2, tc = lane & 3;
#pragma unroll
    for (int nt = 0; nt < 8; nt++) {
        int n0 = nt * 8 + 2 * tc;
        float2 r = __ldg((const float2*)(Rbase + n0));
        float c0 = acc[nt][0] + r.x, c1 = acc[nt][1] + r.y;
        float c2 = acc[nt][2] + r.x, c3 = acc[nt][3] + r.y;
        if (do_relu) {
            c0 = fmaxf(c0, 0.f); c1 = fmaxf(c1, 0.f);
            c2 = fmaxf(c2, 0.f); c3 = fmaxf(c3, 0.f);
        }
        if (store) {
            int s = nt >> 1, o = (nt & 1) * 2;
            hilo2(c0, c1, fh[4 * s + o],     fl[4 * s + o]);
            hilo2(c2, c3, fh[4 * s + o + 1], fl[4 * s + o + 1]);
        }
        float m0 = fmaxf(c0, c2), m1 = fmaxf(c1, c3);
        m0 = fmaxf(m0, __shfl_xor_sync(0xffffffffu, m0, 4));
        m0 = fmaxf(m0, __shfl_xor_sync(0xffffffffu, m0, 8));
        m0 = fmaxf(m0, __shfl_xor_sync(0xffffffffu, m0, 16));
        m1 = fmaxf(m1, __shfl_xor_sync(0xffffffffu, m1, 4));
        m1 = fmaxf(m1, __shfl_xor_sync(0xffffffffu, m1, 8));
        m1 = fmaxf(m1, __shfl_xor_sync(0xffffffffu, m1, 16));
        if (tg == 0) *(float2*)(outp + n0) = make_float2(m0, m1);
    }
}

__global__ __launch_bounds__(256, 1) void edge_mlp_kernel(
    const float* __restrict__ x, float* __restrict__ out) {

    extern __shared__ char sm[];
    int t = threadIdx.x, lane = t & 31, w = t >> 5;

    for (int i = t; i < 100352 / 16; i += 256)
        ((uint4*)sm)[i] = __ldg((const uint4*)g_Wpk + i);
    __syncthreads();

    uint32_t smb = smem_to_u32(sm);
    int tg = lane >> 2, tc = lane & 3;
    int n_in_pair = (lane & 7) + ((lane >> 4) & 1) * 8;
    int kh = (lane >> 3) & 1;
    uint32_t bHb = smb + n_in_pair * 784 + kh * 16;
    uint32_t bLb = bHb + WBYTES;

    for (int p = blockIdx.x * 8 + w; p < TOTPTS; p += 148 * 8) {
        int b = p >> 12;

        uint32_t f1h[16], f1l[16], f2h[16], f2l[16], f3h[16], f3l[16];

        {
            int j0 = __ldg(g_idx + p * KNN + tg);
            int j1 = __ldg(g_idx + p * KNN + tg + 8);
            const float* P  = g_L + p * 256;
            const float* Q0 = g_Q + ((b << 12) + j0) * 64;
            const float* Q1 = g_Q + ((b << 12) + j1) * 64;
            float hm[16];
#pragma unroll
            for (int s = 0; s < 4; s++) {
                int c = 16 * s + 2 * tc;
                float2 p0 = __ldg((const float2*)(P + c));
                float2 p1 = __ldg((const float2*)(P + c + 8));
                float2 q00 = __ldg((const float2*)(Q0 + c));
                float2 q01 = __ldg((const float2*)(Q0 + c + 8));
                float2 q10 = __ldg((const float2*)(Q1 + c));
                float2 q11 = __ldg((const float2*)(Q1 + c + 8));
                float a0x = fmaxf(p0.x + q00.x, 0.f), a0y = fmaxf(p0.y + q00.y, 0.f);
                float a1x = fmaxf(p0.x + q10.x, 0.f), a1y = fmaxf(p0.y + q10.y, 0.f);
                float a2x = fmaxf(p1.x + q01.x, 0.f), a2y = fmaxf(p1.y + q01.y, 0.f);
                float a3x = fmaxf(p1.x + q11.x, 0.f), a3y = fmaxf(p1.y + q11.y, 0.f);
                hilo2(a0x, a0y, f1h[4 * s + 0], f1l[4 * s + 0]);
                hilo2(a1x, a1y, f1h[4 * s + 1], f1l[4 * s + 1]);
                hilo2(a2x, a2y, f1h[4 * s + 2], f1l[4 * s + 2]);
                hilo2(a3x, a3y, f1h[4 * s + 3], f1l[4 * s + 3]);
                hm[4 * s + 0] = fmaxf(a0x, a1x);
                hm[4 * s + 1] = fmaxf(a0y, a1y);
                hm[4 * s + 2] = fmaxf(a2x, a3x);
                hm[4 * s + 3] = fmaxf(a2y, a3y);
            }
#pragma unroll
            for (int i = 0; i < 16; i++) {
                float mv = hm[i];
                mv = fmaxf(mv, __shfl_xor_sync(0xffffffffu, mv, 4));
                mv = fmaxf(mv, __shfl_xor_sync(0xffffffffu, mv, 8));
                mv = fmaxf(mv, __shfl_xor_sync(0xffffffffu, mv, 16));
                hm[i] = mv;
            }
            if (tg == 0) {
                float* dst = out + p * 320 + 192;
#pragma unroll
                for (int s = 0; s < 4; s++) {
                    int c = 16 * s + 2 * tc;
                    *(float2*)(dst + c)     = make_float2(hm[4 * s + 0], hm[4 * s + 1]);
                    *(float2*)(dst + c + 8) = make_float2(hm[4 * s + 2], hm[4 * s + 3]);
                }
            }
            float2 xv = __ldg((const float2*)(x + p * 64 + lane * 2));
            *(float2*)(out + p * 320 + 256 + lane * 2) = xv;
        }

        float acc[8][4];

#pragma unroll
        for (int i = 0; i < 8; i++)
#pragma unroll
            for (int q2 = 0; q2 < 4; q2++) acc[i][q2] = 0.f;
#pragma unroll
        for (int s = 0; s < 4; s++)
            mma_chunk(f1h[4*s], f1h[4*s+1], f1h[4*s+2], f1h[4*s+3],
                      f1l[4*s], f1l[4*s+1], f1l[4*s+2], f1l[4*s+3],
                      bHb + (0 + 16 * s) * 2, bLb + (0 + 16 * s) * 2, acc);
        epi(acc, g_L + p * 256 + 64, true, f2h, f2l, true,
            out + p * 320 + 128, lane);

#pragma unroll
        for (int i = 0; i < 8; i++)
#pragma unroll
            for (int q2 = 0; q2 < 4; q2++) acc[i][q2] = 0.f;
#pragma unroll
        for (int s = 0; s < 4; s++)
            mma_chunk(f2h[4*s], f2h[4*s+1], f2h[4*s+2], f2h[4*s+3],
                      f2l[4*s], f2l[4*s+1], f2l[4*s+2], f2l[4*s+3],
                      bHb + (64 + 16 * s) * 2, bLb + (64 + 16 * s) * 2, acc);
#pragma unroll
        for (int s = 4; s < 8; s++)
            mma_chunk(f1h[4*(s-4)], f1h[4*(s-4)+1], f1h[4*(s-4)+2], f1h[4*(s-4)+3],
                      f1l[4*(s-4)], f1l[4*(s-4)+1], f1l[4*(s-4)+2], f1l[4*(s-4)+3],
                      bHb + (64 + 16 * s) * 2, bLb + (64 + 16 * s) * 2, acc);
        epi(acc, g_L + p * 256 + 128, true, f3h, f3l, true,
            out + p * 320 + 64, lane);

#pragma unroll
        for (int i = 0; i < 8; i++)
#pragma unroll
            for (int q2 = 0; q2 < 4; q2++) acc[i][q2] = 0.f;
#pragma unroll
        for (int s = 0; s < 4; s++)
            mma_chunk(f3h[4*s], f3h[4*s+1], f3h[4*s+2], f3h[4*s+3],
                      f3l[4*s], f3l[4*s+1], f3l[4*s+2], f3l[4*s+3],
                      bHb + (192 + 16 * s) * 2, bLb + (192 + 16 * s) * 2, acc);
#pragma unroll
        for (int s = 4; s < 8; s++)
            mma_chunk(f2h[4*(s-4)], f2h[4*(s-4)+1], f2h[4*(s-4)+2], f2h[4*(s-4)+3],
                      f2l[4*(s-4)], f2l[4*(s-4)+1], f2l[4*(s-4)+2], f2l[4*(s-4)+3],
                      bHb + (192 + 16 * s) * 2, bLb + (192 + 16 * s) * 2, acc);
#pragma unroll
        for (int s = 8; s < 12; s++)
            mma_chunk(f1h[4*(s-8)], f1h[4*(s-8)+1], f1h[4*(s-8)+2], f1h[4*(s-8)+3],
                      f1l[4*(s-8)], f1l[4*(s-8)+1], f1l[4*(s-8)+2], f1l[4*(s-8)+3],
                      bHb + (192 + 16 * s) * 2, bLb + (192 + 16 * s) * 2, acc);
        epi(acc, g_L + p * 256 + 192, false, f2h, f2l, false,
            out + p * 320, lane);
    }
}

// ---------------------------------------------------------------------------
extern "C" void kernel_launch(void* const* d_in, const int* in_sizes, int n_in,
                              void* d_out, int out_size) {
    const float* x   = (const float*)d_in[0];
    const float* pos = (const float*)d_in[1];
    const float* Wf  = (const float*)d_in[2];
    const float* bf  = (const float*)d_in[3];
    const float* Wm1 = (const float*)d_in[4];
    const float* bm1 = (const float*)d_in[5];
    const float* Wm2 = (const float*)d_in[6];
    const float* bm2 = (const float*)d_in[7];
    const float* Wl  = (const float*)d_in[8];
    const float* bl  = (const float*)d_in[9];
    float* out = (float*)d_out;

    cudaFuncSetAttribute(edge_mlp_kernel,
                         cudaFuncAttributeMaxDynamicSharedMemorySize,
                         MAIN_SMEM_BYTES);

    init_w_kernel<<<96, 256>>>(Wm1, Wm2, Wl);
    knn_kernel<<<TOTPTS / KQ, 128>>>(pos);
    pre_kernel<<<256, 256>>>(x, Wf, bf, Wm1, bm1, Wm2, bm2, Wl, bl);
    edge_mlp_kernel<<<148, 256, MAIN_SMEM_BYTES>>>(x, out);
}

// round 15
// speedup vs baseline: 1.4585x; 1.4585x over previous
#include <cuda_runtime.h>
#include <cuda_bf16.h>
#include <cstdint>

#define TOTPTS 16384
#define NPTS   4096
#define KNN    16

// ---- knn v7 config: 16 queries/block x 16 subs; phase A on first 1024 only ----
#define QPB  16
#define SUBS 16
#define TILE 256
#define PRE_N 1024               // candidates scanned in phase A (valid-subset tau)
#define KNN_SMEM_BYTES (TILE * 16 + QPB * TILE * 4 + QPB * KNN * 4 * 2 + QPB * 8)

// ---- edge_mlp smem: weights only ----
#define WBYTES  50176            // 64*392*2
#define MAIN_SMEM_BYTES 100352   // hi + lo

// Scratch (allocation-free rule: device globals)
__device__ __align__(16) float g_L[TOTPTS * 256];   // [P | R1 | R2 | R3] per point
__device__ __align__(16) float g_Q[TOTPTS * 64];    // Q per point
__device__ int g_idx[TOTPTS * KNN];
__device__ __align__(16) unsigned char g_Wpk[100352]; // packed bf16 hi(50176)+lo(50176)

// ===================== helpers =====================
__device__ __forceinline__ uint32_t smem_to_u32(const void* p) {
    uint32_t a;
    asm("{ .reg .u64 t; cvta.to.shared.u64 t, %1; cvt.u32.u64 %0, t; }" : "=r"(a) : "l"(p));
    return a;
}
#define LDSM4(r0, r1, r2, r3, addr) \
    asm volatile("ldmatrix.sync.aligned.m8n8.x4.shared.b16 {%0,%1,%2,%3}, [%4];" \
        : "=r"(r0), "=r"(r1), "=r"(r2), "=r"(r3) : "r"(addr))
#define MMA16816(c, a0, a1, a2, a3, b0, b1) \
    asm volatile("mma.sync.aligned.m16n8k16.row.col.f32.bf16.bf16.f32 " \
        "{%0,%1,%2,%3}, {%4,%5,%6,%7}, {%8,%9}, {%0,%1,%2,%3};" \
        : "+f"((c)[0]), "+f"((c)[1]), "+f"((c)[2]), "+f"((c)[3]) \
        : "r"(a0), "r"(a1), "r"(a2), "r"(a3), "r"(b0), "r"(b1))

__device__ __forceinline__ void hilo2(float a, float b, uint32_t& h, uint32_t& l) {
    __nv_bfloat16 ha = __float2bfloat16(a), hb = __float2bfloat16(b);
    float ra = a - __bfloat162float(ha), rb = b - __bfloat162float(hb);
    __nv_bfloat162 H; H.x = ha; H.y = hb;
    __nv_bfloat162 L; L.x = __float2bfloat16(ra); L.y = __float2bfloat16(rb);
    h = *(uint32_t*)&H; l = *(uint32_t*)&L;
}

// ---------------------------------------------------------------------------
// KNN v7: like v6 (R11 passing winner) but phase A scans only the first
// PRE_N candidates. tau from a subset is a PROVABLE upper bound on d16
// (enlarging the candidate set can only shrink the 16th-smallest), just
// looser -> slightly more phase-B passes (model: ~4x -> ~64/query, trivial).
// Per tile, at most TILE candidates can pass for a query and scnt resets
// every tile, so the slot index is < TILE by construction (clamp is a
// provable no-op kept for defense). Phase B + refine identical to v6:
// exact fp32 formula, dedup vs seeds -> selection identical to every
// passing round.
// ---------------------------------------------------------------------------
__global__ __launch_bounds__(256) void knn_kernel(const float* __restrict__ pos) {
    extern __shared__ char kshm[];
    float4* sp    = (float4*)kshm;                                     // 4 KB
    int*    bufI  = (int*)(kshm + TILE * 16);                          // 16 KB
    float*  seedD = (float*)(kshm + TILE * 16 + QPB * TILE * 4);
    int*    seedI = (int*)(kshm + TILE * 16 + QPB * TILE * 4 + QPB * KNN * 4);
    int*    scnt  = (int*)(kshm + TILE * 16 + QPB * TILE * 4 + QPB * KNN * 8);
    float*  stau  = (float*)(kshm + TILE * 16 + QPB * TILE * 4 + QPB * KNN * 8 + QPB * 4);

    int t   = threadIdx.x;
    int ql  = t >> 4;                      // 0..15 query within block
    int sub = t & 15;
    int qg  = blockIdx.x * QPB + ql;
    int b   = qg >> 12;
    int q   = qg & 4095;
    const float* pb = pos + b * NPTS * 3;

    if (t < QPB) scnt[t] = 0;

    float qx = __ldg(pb + q * 3 + 0);
    float qy = __ldg(pb + q * 3 + 1);
    float qz = __ldg(pb + q * 3 + 2);
    float qn = qx * qx + qy * qy + qz * qz;

    float rqx = 0.f, rqy = 0.f, rqz = 0.f, rqn = 0.f;
    if (t < QPB) {
        int rq = (blockIdx.x * QPB + t) & 4095;
        rqx = __ldg(pb + rq * 3 + 0);
        rqy = __ldg(pb + rq * 3 + 1);
        rqz = __ldg(pb + rq * 3 + 2);
        rqn = rqx * rqx + rqy * rqy + rqz * rqz;
    }

    // ---- Phase A: per-(query,sub) top-1 over first PRE_N candidates ----
    float s0 = 3.0e38f;
    int   i0 = 0;

    for (int t0 = 0; t0 < PRE_N; t0 += TILE) {
        __syncthreads();
        {
            int j = t0 + t;
            float x = pb[j * 3 + 0], y = pb[j * 3 + 1], z = pb[j * 3 + 2];
            sp[t] = make_float4(x, y, z, x * x + y * y + z * z);
        }
        __syncthreads();
#pragma unroll 8
        for (int jj = 0; jj < TILE / SUBS; jj++) {
            int jl = sub + (jj << 4);
            float4 c = sp[jl];
            float dot = qx * c.x;
            dot = fmaf(qy, c.y, dot);
            dot = fmaf(qz, c.z, dot);
            float d2 = fmaf(dot, -2.0f, qn + c.w);
            int jg = t0 + jl;
            if (d2 < s0 && jg != q) { s0 = d2; i0 = jg; }
        }
    }
    seedD[ql * KNN + sub] = s0;
    seedI[ql * KNN + sub] = i0;
    __syncthreads();

    // ---- Seed refine state: 16 distinct sub-minima; tau0 = their max ----
    float dv[KNN];
    int   iv[KNN];
    float dmax = 0.f;
    int   amax = 0;
    if (t < QPB) {
#pragma unroll
        for (int r = 0; r < KNN; r++) {
            dv[r] = seedD[t * KNN + r];
            iv[r] = seedI[t * KNN + r];
        }
        dmax = dv[0]; amax = 0;
#pragma unroll
        for (int r = 1; r < KNN; r++)
            if (dv[r] > dmax) { dmax = dv[r]; amax = r; }
        stau[t] = dmax;
    }

    // ---- Phase B: tau-filter + per-tile refine (exact, dedup vs seeds) ----
    for (int t0 = 0; t0 < NPTS; t0 += TILE) {
        __syncthreads();
        {
            int j = t0 + t;
            float x = pb[j * 3 + 0], y = pb[j * 3 + 1], z = pb[j * 3 + 2];
            sp[t] = make_float4(x, y, z, x * x + y * y + z * z);
        }
        __syncthreads();

        float tau = stau[ql];
        int*  bI  = bufI + ql * TILE;

#pragma unroll 8
        for (int jj = 0; jj < TILE / SUBS; jj++) {
            int jl = sub + (jj << 4);
            float4 c = sp[jl];
            float dot = qx * c.x;
            dot = fmaf(qy, c.y, dot);
            dot = fmaf(qz, c.z, dot);
            float d2 = fmaf(dot, -2.0f, qn + c.w);
            int jg = t0 + jl;
            if (d2 < tau && jg != q) {
                int slot = atomicAdd(&scnt[ql], 1);
                if (slot >= TILE) slot = TILE - 1;   // unreachable; defensive
                bI[slot] = jl;
            }
        }
        __syncthreads();

        if (t < QPB) {
            int n = scnt[t];
            if (n > TILE) n = TILE;
            const int* rI = bufI + t * TILE;
            for (int e = 0; e < n; e++) {
                int jl = rI[e];
                float4 c = sp[jl];
                float dot = rqx * c.x;
                dot = fmaf(rqy, c.y, dot);
                dot = fmaf(rqz, c.z, dot);
                float d2 = fmaf(dot, -2.0f, rqn + c.w);
                if (d2 < dmax) {
                    int jg = t0 + jl;
                    bool dup = false;
#pragma unroll
                    for (int r = 0; r < KNN; r++) dup = dup || (iv[r] == jg);
                    if (!dup) {
                        dv[amax] = d2; iv[amax] = jg;
                        dmax = dv[0]; amax = 0;
#pragma unroll
                        for (int r = 1; r < KNN; r++)
                            if (dv[r] > dmax) { dmax = dv[r]; amax = r; }
                    }
                }
            }
            scnt[t] = 0;
            stau[t] = dmax;
        }
    }

    if (t < QPB) {
        int obase = (blockIdx.x * QPB + t) * KNN;
#pragma unroll
        for (int r = 0; r < KNN; r++) g_idx[obase + r] = iv[r];
    }
}

// ---------------------------------------------------------------------------
// Per-point precompute (unchanged)
// ---------------------------------------------------------------------------
__global__ __launch_bounds__(256) void pre_kernel(
    const float* __restrict__ x,
    const float* __restrict__ Wf,  const float* __restrict__ bf,
    const float* __restrict__ Wm1, const float* __restrict__ bm1,
    const float* __restrict__ Wm2, const float* __restrict__ bm2,
    const float* __restrict__ Wl,  const float* __restrict__ bl) {

    __shared__ float sw[4096];
    __shared__ float sx[64 * 68];

    int t   = threadIdx.x;
    int pt0 = blockIdx.x * 64;

    for (int i = t; i < 4096; i += 256) {
        int r = i >> 6, c = i & 63;
        sx[c * 68 + r] = __ldg(x + (pt0 + r) * 64 + c);
    }

    int m0 = (t & 15) * 4;
    int n0 = (t >> 4) * 4;

    for (int sect = 0; sect < 5; sect++) {
        __syncthreads();
        for (int i = t; i < 4096; i += 256) {
            float v;
            if      (sect == 0) v = __ldg(Wf + i)        - __ldg(Wf + 8192 + i);
            else if (sect == 1) v = __ldg(Wf + 4096 + i) + __ldg(Wf + 8192 + i);
            else if (sect == 2) v = __ldg(Wm1 + 4096 + i);
            else if (sect == 3) v = __ldg(Wm2 + 8192 + i);
            else                v = __ldg(Wl + 12288 + i);
            sw[i] = v;
        }
        __syncthreads();

        float acc[4][4];
#pragma unroll
        for (int a = 0; a < 4; a++)
#pragma unroll
            for (int bq = 0; bq < 4; bq++) acc[a][bq] = 0.0f;

#pragma unroll 4
        for (int k = 0; k < 64; k++) {
            float4 av = *(const float4*)(sx + k * 68 + m0);
            float4 wv = *(const float4*)(sw + k * 64 + n0);
            float aa[4] = {av.x, av.y, av.z, av.w};
            float ww[4] = {wv.x, wv.y, wv.z, wv.w};
#pragma unroll
            for (int mi = 0; mi < 4; mi++)
#pragma unroll
                for (int ni = 0; ni < 4; ni++)
                    acc[mi][ni] = fmaf(aa[mi], ww[ni], acc[mi][ni]);
        }

        float4 bb = make_float4(0.f, 0.f, 0.f, 0.f);
        const float* bp = (sect == 0) ? bf : (sect == 2) ? bm1
                         : (sect == 3) ? bm2 : (sect == 4) ? bl : nullptr;
        if (bp) bb = __ldg((const float4*)(bp + n0));

#pragma unroll
        for (int mi = 0; mi < 4; mi++) {
            int pt = pt0 + m0 + mi;
            float4 o = make_float4(acc[mi][0] + bb.x, acc[mi][1] + bb.y,
                                   acc[mi][2] + bb.z, acc[mi][3] + bb.w);
            float* dst;
            if (sect == 1) dst = g_Q + pt * 64 + n0;
            else {
                int off = (sect == 0) ? 0 : (sect == 2) ? 64 : (sect == 3) ? 128 : 192;
                dst = g_L + pt * 256 + off + n0;
            }
            *(float4*)dst = o;
        }
    }
}

// ---------------------------------------------------------------------------
// Weight repack (unchanged)
// ---------------------------------------------------------------------------
__global__ __launch_bounds__(256) void init_w_kernel(
    const float* __restrict__ Wm1, const float* __restrict__ Wm2,
    const float* __restrict__ Wl) {
    int e = blockIdx.x * 256 + threadIdx.x;          // 0..24575
    const float* src; int colbase;
    if (e < 4096)       { src = Wm1; colbase = 0; }
    else if (e < 12288) { src = Wm2; colbase = 64;  e -= 4096; }
    else                { src = Wl;  colbase = 192; e -= 12288; }
    int k = e >> 6, n = e & 63;
    float v = src[k * 64 + n];
    __nv_bfloat16 h = __float2bfloat16(v);
    __nv_bfloat16 l = __float2bfloat16(v - __bfloat162float(h));
    uint32_t off = (uint32_t)(n * 392 + colbase + k) * 2;
    *(__nv_bfloat16*)(g_Wpk + off)         = h;
    *(__nv_bfloat16*)(g_Wpk + 50176 + off) = l;
}

// ---------------------------------------------------------------------------
// edge_mlp (unchanged R10/R11 winner)
// ---------------------------------------------------------------------------
__device__ __forceinline__ void mma_chunk(
    uint32_t a0h, uint32_t a1h, uint32_t a2h, uint32_t a3h,
    uint32_t a0l, uint32_t a1l, uint32_t a2l, uint32_t a3l,
    uint32_t bH, uint32_t bL, float acc[8][4]) {
    uint32_t bh[4][4], bl[4][4];
#pragma unroll
    for (int pr = 0; pr < 4; pr++) {
        LDSM4(bh[pr][0], bh[pr][1], bh[pr][2], bh[pr][3], bH + pr * (16 * 784));
        LDSM4(bl[pr][0], bl[pr][1], bl[pr][2], bl[pr][3], bL + pr * (16 * 784));
    }
#pragma unroll
    for (int pr = 0; pr < 4; pr++) {
        MMA16816(acc[2 * pr],     a0h, a1h, a2h, a3h, bh[pr][0], bh[pr][1]);
        MMA16816(acc[2 * pr + 1], a0h, a1h, a2h, a3h, bh[pr][2], bh[pr][3]);
    }
#pragma unroll
    for (int pr = 0; pr < 4; pr++) {
        MMA16816(acc[2 * pr],     a0h, a1h, a2h, a3h, bl[pr][0], bl[pr][1]);
        MMA16816(acc[2 * pr + 1], a0h, a1h, a2h, a3h, bl[pr][2], bl[pr][3]);
    }
#pragma unroll
    for (int pr = 0; pr < 4; pr++) {
        MMA16816(acc[2 * pr],     a0l, a1l, a2l, a3l, bh[pr][0], bh[pr][1]);
        MMA16816(acc[2 * pr + 1], a0l, a1l, a2l, a3l, bh[pr][2], bh[pr][3]);
    }
}

__device__ __forceinline__ void epi(
    float acc[8][4], const float* __restrict__ Rbase, bool do_relu,
    uint32_t* fh, uint32_t* fl, bool store,
    float* __restrict__ outp, int lane) {
    int tg = lane >> 2, tc = lane & 3;
#pragma unroll
    for (int nt = 0; nt < 8; nt++) {
        int n0 = nt * 8 + 2 * tc;
        float2 r = __ldg((const float2*)(Rbase + n0));
        float c0 = acc[nt][0] + r.x, c1 = acc[nt][1] + r.y;
        float c2 = acc[nt][2] + r.x, c3 = acc[nt][3] + r.y;
        if (do_relu) {
            c0 = fmaxf(c0, 0.f); c1 = fmaxf(c1, 0.f);
            c2 = fmaxf(c2, 0.f); c3 = fmaxf(c3, 0.f);
        }
        if (store) {
            int s = nt >> 1, o = (nt & 1) * 2;
            hilo2(c0, c1, fh[4 * s + o],     fl[4 * s + o]);
            hilo2(c2, c3, fh[4 * s + o + 1], fl[4 * s + o + 1]);
        }
        float m0 = fmaxf(c0, c2), m1 = fmaxf(c1, c3);
        m0 = fmaxf(m0, __shfl_xor_sync(0xffffffffu, m0, 4));
        m0 = fmaxf(m0, __shfl_xor_sync(0xffffffffu, m0, 8));
        m0 = fmaxf(m0, __shfl_xor_sync(0xffffffffu, m0, 16));
        m1 = fmaxf(m1, __shfl_xor_sync(0xffffffffu, m1, 4));
        m1 = fmaxf(m1, __shfl_xor_sync(0xffffffffu, m1, 8));
        m1 = fmaxf(m1, __shfl_xor_sync(0xffffffffu, m1, 16));
        if (tg == 0) *(float2*)(outp + n0) = make_float2(m0, m1);
    }
}

__global__ __launch_bounds__(256, 1) void edge_mlp_kernel(
    const float* __restrict__ x, float* __restrict__ out) {

    extern __shared__ char sm[];
    int t = threadIdx.x, lane = t & 31, w = t >> 5;

    for (int i = t; i < 100352 / 16; i += 256)
        ((uint4*)sm)[i] = __ldg((const uint4*)g_Wpk + i);
    __syncthreads();

    uint32_t smb = smem_to_u32(sm);
    int tg = lane >> 2, tc = lane & 3;
    int n_in_pair = (lane & 7) + ((lane >> 4) & 1) * 8;
    int kh = (lane >> 3) & 1;
    uint32_t bHb = smb + n_in_pair * 784 + kh * 16;
    uint32_t bLb = bHb + WBYTES;

    for (int p = blockIdx.x * 8 + w; p < TOTPTS; p += 148 * 8) {
        int b = p >> 12;

        uint32_t f1h[16], f1l[16], f2h[16], f2l[16], f3h[16], f3l[16];

        // ---- Gather: H1 fragments direct from global + fused H1 max ----
        {
            int j0 = __ldg(g_idx + p * KNN + tg);
            int j1 = __ldg(g_idx + p * KNN + tg + 8);
            const float* P  = g_L + p * 256;
            const float* Q0 = g_Q + ((b << 12) + j0) * 64;
            const float* Q1 = g_Q + ((b << 12) + j1) * 64;
            float hm[16];
#pragma unroll
            for (int s = 0; s < 4; s++) {
                int c = 16 * s + 2 * tc;
                float2 p0 = __ldg((const float2*)(P + c));
                float2 p1 = __ldg((const float2*)(P + c + 8));
                float2 q00 = __ldg((const float2*)(Q0 + c));
                float2 q01 = __ldg((const float2*)(Q0 + c + 8));
                float2 q10 = __ldg((const float2*)(Q1 + c));
                float2 q11 = __ldg((const float2*)(Q1 + c + 8));
                float a0x = fmaxf(p0.x + q00.x, 0.f), a0y = fmaxf(p0.y + q00.y, 0.f);
                float a1x = fmaxf(p0.x + q10.x, 0.f), a1y = fmaxf(p0.y + q10.y, 0.f);
                float a2x = fmaxf(p1.x + q01.x, 0.f), a2y = fmaxf(p1.y + q01.y, 0.f);
                float a3x = fmaxf(p1.x + q11.x, 0.f), a3y = fmaxf(p1.y + q11.y, 0.f);
                hilo2(a0x, a0y, f1h[4 * s + 0], f1l[4 * s + 0]);
                hilo2(a1x, a1y, f1h[4 * s + 1], f1l[4 * s + 1]);
                hilo2(a2x, a2y, f1h[4 * s + 2], f1l[4 * s + 2]);
                hilo2(a3x, a3y, f1h[4 * s + 3], f1l[4 * s + 3]);
                hm[4 * s + 0] = fmaxf(a0x, a1x);
                hm[4 * s + 1] = fmaxf(a0y, a1y);
                hm[4 * s + 2] = fmaxf(a2x, a3x);
                hm[4 * s + 3] = fmaxf(a2y, a3y);
            }
#pragma unroll
            for (int i = 0; i < 16; i++) {
                float mv = hm[i];
                mv = fmaxf(mv, __shfl_xor_sync(0xffffffffu, mv, 4));
                mv = fmaxf(mv, __shfl_xor_sync(0xffffffffu, mv, 8));
                mv = fmaxf(mv, __shfl_xor_sync(0xffffffffu, mv, 16));
                hm[i] = mv;
            }
            if (tg == 0) {
                float* dst = out + p * 320 + 192;
#pragma unroll
                for (int s = 0; s < 4; s++) {
                    int c = 16 * s + 2 * tc;
                    *(float2*)(dst + c)     = make_float2(hm[4 * s + 0], hm[4 * s + 1]);
                    *(float2*)(dst + c + 8) = make_float2(hm[4 * s + 2], hm[4 * s + 3]);
                }
            }
            float2 xv = __ldg((const float2*)(x + p * 64 + lane * 2));
            *(float2*)(out + p * 320 + 256 + lane * 2) = xv;
        }

        float acc[8][4];

        // ---- Layer 2: H2 = relu(H1 @ Ws2 + R1); B k-cols 0..63 ----
#pragma unroll
        for (int i = 0; i < 8; i++)
#pragma unroll
            for (int q2 = 0; q2 < 4; q2++) acc[i][q2] = 0.f;
#pragma unroll
        for (int s = 0; s < 4; s++)
            mma_chunk(f1h[4*s], f1h[4*s+1], f1h[4*s+2], f1h[4*s+3],
                      f1l[4*s], f1l[4*s+1], f1l[4*s+2], f1l[4*s+3],
                      bHb + (0 + 16 * s) * 2, bLb + (0 + 16 * s) * 2, acc);
        epi(acc, g_L + p * 256 + 64, true, f2h, f2l, true,
            out + p * 320 + 128, lane);

        // ---- Layer 3: H3 = relu([H2|H1] @ Ws3 + R2); B k-cols 64..191 ----
#pragma unroll
        for (int i = 0; i < 8; i++)
#pragma unroll
            for (int q2 = 0; q2 < 4; q2++) acc[i][q2] = 0.f;
#pragma unroll
        for (int s = 0; s < 4; s++)
            mma_chunk(f2h[4*s], f2h[4*s+1], f2h[4*s+2], f2h[4*s+3],
                      f2l[4*s], f2l[4*s+1], f2l[4*s+2], f2l[4*s+3],
                      bHb + (64 + 16 * s) * 2, bLb + (64 + 16 * s) * 2, acc);
#pragma unroll
        for (int s = 4; s < 8; s++)
            mma_chunk(f1h[4*(s-4)], f1h[4*(s-4)+1], f1h[4*(s-4)+2], f1h[4*(s-4)+3],
                      f1l[4*(s-4)], f1l[4*(s-4)+1], f1l[4*(s-4)+2], f1l[4*(s-4)+3],
                      bHb + (64 + 16 * s) * 2, bLb + (64 + 16 * s) * 2, acc);
        epi(acc, g_L + p * 256 + 128, true, f3h, f3l, true,
            out + p * 320 + 64, lane);

        // ---- Layer 4: H4 = [H3|H2|H1] @ Ws4 + R3 (no relu); B k-cols 192..383 ----
#pragma unroll
        for (int i = 0; i < 8; i++)
#pragma unroll
            for (int q2 = 0; q2 < 4; q2++) acc[i][q2] = 0.f;
#pragma unroll
        for (int s = 0; s < 4; s++)
            mma_chunk(f3h[4*s], f3h[4*s+1], f3h[4*s+2], f3h[4*s+3],
                      f3l[4*s], f3l[4*s+1], f3l[4*s+2], f3l[4*s+3],
                      bHb + (192 + 16 * s) * 2, bLb + (192 + 16 * s) * 2, acc);
#pragma unroll
        for (int s = 4; s < 8; s++)
            mma_chunk(f2h[4*(s-4)], f2h[4*(s-4)+1], f2h[4*(s-4)+2], f2h[4*(s-4)+3],
                      f2l[4*(s-4)], f2l[4*(s-4)+1], f2l[4*(s-4)+2], f2l[4*(s-4)+3],
                      bHb + (192 + 16 * s) * 2, bLb + (192 + 16 * s) * 2, acc);
#pragma unroll
        for (int s = 8; s < 12; s++)
            mma_chunk(f1h[4*(s-8)], f1h[4*(s-8)+1], f1h[4*(s-8)+2], f1h[4*(s-8)+3],
                      f1l[4*(s-8)], f1l[4*(s-8)+1], f1l[4*(s-8)+2], f1l[4*(s-8)+3],
                      bHb + (192 + 16 * s) * 2, bLb + (192 + 16 * s) * 2, acc);
        epi(acc, g_L + p * 256 + 192, false, f2h, f2l, false,
            out + p * 320, lane);
    }
}

// ---------------------------------------------------------------------------
extern "C" void kernel_launch(void* const* d_in, const int* in_sizes, int n_in,
                              void* d_out, int out_size) {
    const float* x   = (const float*)d_in[0];
    const float* pos = (const float*)d_in[1];
    const float* Wf  = (const float*)d_in[2];
    const float* bf  = (const float*)d_in[3];
    const float* Wm1 = (const float*)d_in[4];
    const float* bm1 = (const float*)d_in[5];
    const float* Wm2 = (const float*)d_in[6];
    const float* bm2 = (const float*)d_in[7];
    const float* Wl  = (const float*)d_in[8];
    const float* bl  = (const float*)d_in[9];
    float* out = (float*)d_out;

    cudaFuncSetAttribute(knn_kernel,
                         cudaFuncAttributeMaxDynamicSharedMemorySize,
                         KNN_SMEM_BYTES);
    cudaFuncSetAttribute(edge_mlp_kernel,
                         cudaFuncAttributeMaxDynamicSharedMemorySize,
                         MAIN_SMEM_BYTES);

    init_w_kernel<<<96, 256>>>(Wm1, Wm2, Wl);
    knn_kernel<<<TOTPTS / QPB, 256, KNN_SMEM_BYTES>>>(pos);
    pre_kernel<<<256, 256>>>(x, Wf, bf, Wm1, bm1, Wm2, bm2, Wl, bl);
    edge_mlp_kernel<<<148, 256, MAIN_SMEM_BYTES>>>(x, out);
}